// round 10
// baseline (speedup 1.0000x reference)
#include <cuda_runtime.h>
#include <cstdint>
#include <cstddef>

// Depthwise conv1d: B=8, L=16384, C=512, K=31, SAME, fp32.
// RCH=64, cp.async -> warp-private SMEM slab ring (3 x 16 rows, 48 KB) +
// f32x2 32-slot ring-accumulator. Code-size-minimized: main stencil exists
// as ONE 32-step body run twice (ring phase repeats mod 32); boundary
// handling is runtime-predicated in the copier (no template duplication).
// Stream step s = 0..95, input q = l0-16+s adds w[k] to slot (s-1-k)&31;
// output l0+s-31 stored from slot (s+1)&31 at end of step s (31<=s<=94).

constexpr int B_   = 8;
constexpr int L_   = 16384;
constexpr int C_   = 512;
constexpr int K_   = 31;
constexpr int RCH  = 64;           // L outputs per block
constexpr int TPB  = 128;          // 4 warps; warp owns 32 channel pairs
constexpr int CW   = C_ / 2;       // 256 u64 per L-row
constexpr int SLAB = 16;           // L-rows per smem slab
constexpr int ROWB = 2048;         // bytes per full L-row (512 floats)
constexpr int NSLAB = 6;           // 96 stream rows (need 95; row 95 inert)

using u64 = unsigned long long;

__device__ __forceinline__ u64 ffma2(u64 a, u64 b, u64 c) {
    u64 d;
    asm("fma.rn.f32x2 %0, %1, %2, %3;" : "=l"(d) : "l"(a), "l"(b), "l"(c));
    return d;
}
__device__ __forceinline__ void stg_cs(u64* p, u64 v) {
    asm volatile("st.global.cs.b64 [%0], %1;" :: "l"(p), "l"(v));
}
__device__ __forceinline__ void cpa16(unsigned saddr, const void* gptr, unsigned sz) {
    asm volatile("cp.async.cg.shared.global [%0], [%1], 16, %2;\n"
                 :: "r"(saddr), "l"(gptr), "r"(sz));
}
__device__ __forceinline__ void cpcommit() { asm volatile("cp.async.commit_group;\n"); }
template <int N>
__device__ __forceinline__ void cpwait() { asm volatile("cp.async.wait_group %0;\n" :: "n"(N)); }

struct Copier {
    const char* xw;     // x base for (batch, warp's first channel pair)
    unsigned    sbase;  // warp's buffer[0] smem addr
    int         rl;     // lane>>4 (row parity this lane serves)
    int         o16;    // (lane&15)*16 (byte offset within 256B row)
    int         q0;     // l0 - 16

    // One 16-row slab (4 KB/warp) into buffer buf; runtime OOB clamp,
    // SAME padding zero-filled via src_size = 0.
    __device__ __forceinline__ void issue(int slab, int buf) const {
        if (slab >= NSLAB) { cpcommit(); return; }   // uniform group count
        unsigned dst = sbase + (unsigned)buf * (SLAB * 256)
                     + (unsigned)(rl * 256 + o16);
        const int qb = q0 + slab * SLAB + rl;
#pragma unroll
        for (int j = 0; j < 8; ++j) {
            int q = qb + 2 * j;
            int qc = q < 0 ? 0 : (q >= L_ ? L_ - 1 : q);
            unsigned sz = (q >= 0 && q < L_) ? 16u : 0u;
            cpa16(dst + (unsigned)(j * 512), xw + (long)qc * ROWB + o16, sz);
        }
        cpcommit();
    }
};

// 16 steps at ring phase 0 (s === 0..15 mod 32). Full stencil + stores.
__device__ __forceinline__ void slab_p0(const u64* __restrict__ sl, int lane,
                                        const u64* __restrict__ wr,
                                        u64* __restrict__ acc, u64 bb,
                                        u64*& op)
{
#pragma unroll
    for (int u = 0; u < 16; ++u) {
        const u64 v = sl[u * 32 + lane];
#pragma unroll
        for (int k = 0; k < K_; ++k) {
            const int t = (u - 1 - k) & 31;
            acc[t] = ffma2(v, wr[k], acc[t]);
        }
        const int st = (u + 1) & 31;
        stg_cs(op, acc[st]); acc[st] = bb; op += CW;
    }
}

// 16 steps at ring phase 16. When last, step u=15 (s=95) skips its store
// (output belongs to the next chunk); its taps only touch already-stored
// slots' next occupants -> harmless.
__device__ __forceinline__ void slab_p16(const u64* __restrict__ sl, int lane,
                                         const u64* __restrict__ wr,
                                         u64* __restrict__ acc, u64 bb,
                                         u64*& op, bool last)
{
#pragma unroll
    for (int u = 0; u < 16; ++u) {
        const u64 v = sl[u * 32 + lane];
#pragma unroll
        for (int k = 0; k < K_; ++k) {
            const int t = (16 + u - 1 - k) & 31;
            acc[t] = ffma2(v, wr[k], acc[t]);
        }
        const int st = (16 + u + 1) & 31;
        if (u < 15 || !last) {
            stg_cs(op, acc[st]); acc[st] = bb; op += CW;
        }
    }
}

__global__ void __launch_bounds__(TPB, 3)
dwconv_kernel(const float* __restrict__ x, const float* __restrict__ w,
              const float* __restrict__ bias, float* __restrict__ out)
{
    __shared__ __align__(16) u64 sbuf[4][3][SLAB][32];   // 48 KB

    const int lane = threadIdx.x & 31;
    const int warp = threadIdx.x >> 5;
    const int cp   = blockIdx.y * TPB + threadIdx.x;     // channel pair
    const int cp0w = blockIdx.y * TPB + warp * 32;
    const int b    = blockIdx.z;
    const int l0   = blockIdx.x * RCH;

    Copier cc;
    cc.xw    = (const char*)x + (size_t)b * ((size_t)L_ * C_ * 4) + (size_t)cp0w * 8;
    cc.sbase = (unsigned)__cvta_generic_to_shared(&sbuf[warp][0][0][0]);
    cc.rl    = lane >> 4;
    cc.o16   = (lane & 15) * 16;
    cc.q0    = l0 - 16;

    const u64* wg = (const u64*)w;
    u64 wr[K_];
#pragma unroll
    for (int k = 0; k < K_; ++k) wr[k] = wg[k * CW + cp];
    const u64 bb = ((const u64*)bias)[cp];

    u64 acc[32];
#pragma unroll
    for (int i = 0; i < 32; ++i) acc[i] = bb;

    u64* op = (u64*)out + (size_t)b * ((size_t)L_ * CW) + (size_t)l0 * CW + cp;

    cc.issue(0, 0); cc.issue(1, 1); cc.issue(2, 2);
    const u64* sw = &sbuf[warp][0][0][0];

    // ---- ramp slab 0 (s = 0..15): taps k <= s-1, no stores ----
    cpwait<2>(); __syncwarp();
#pragma unroll
    for (int u = 1; u < 16; ++u) {
        const u64 v = sw[u * 32 + lane];
#pragma unroll
        for (int k = 0; k < u; ++k) {
            const int t = u - 1 - k;
            acc[t] = ffma2(v, wr[k], acc[t]);
        }
    }
    __syncwarp(); cc.issue(3, 0);

    // ---- ramp slab 1 (s = 16..31): taps k <= 15+u; first store at s=31 ----
    cpwait<2>(); __syncwarp();
#pragma unroll
    for (int u = 0; u < 16; ++u) {
        const u64 v = sw[(SLAB * 32) + u * 32 + lane];
#pragma unroll
        for (int k = 0; k <= 15 + u; ++k) {
            const int t = 15 + u - k;
            acc[t] = ffma2(v, wr[k], acc[t]);
        }
        if (u == 15) { stg_cs(op, acc[0]); acc[0] = bb; op += CW; }
    }
    __syncwarp(); cc.issue(4, 1);

    // ---- main: 2 x 32-step super-iterations (single code body) ----
    // i=0: slabs 2,3 in bufs 2,0 ; i=1: slabs 4,5 in bufs 1,2.
#pragma unroll 1
    for (int i = 0; i < 2; ++i) {
        const u64* pA = sw + (2 - i)     * (SLAB * 32);  // phase-0 slab
        const u64* pB = sw + (2 * i)     * (SLAB * 32);  // phase-16 slab

        cpwait<2>(); __syncwarp();
        slab_p0(pA, lane, wr, acc, bb, op);
        __syncwarp(); cc.issue(5 + 2 * i, 2 - i);        // real only at i=0

        cpwait<2>(); __syncwarp();
        slab_p16(pB, lane, wr, acc, bb, op, i == 1);
        __syncwarp(); cc.issue(6 + 2 * i, 2 * i);        // dummy commits
    }
}

extern "C" void kernel_launch(void* const* d_in, const int* in_sizes, int n_in,
                              void* d_out, int out_size)
{
    const float* x    = (const float*)d_in[0];   // [B, L, C]
    const float* w    = (const float*)d_in[1];   // [K, C, 1]
    const float* bias = (const float*)d_in[2];   // [C]
    float*       out  = (float*)d_out;           // [B, L, C]

    dim3 grid(L_ / RCH, (C_ / 2) / TPB, B_);     // (256, 2, 8) = 4096 CTAs
    dwconv_kernel<<<grid, TPB>>>(x, w, bias, out);
}